// round 4
// baseline (speedup 1.0000x reference)
#include <cuda_runtime.h>

// Problem constants
#define BB    8
#define TT    2048
#define CIN   7
#define CC    8
#define NCH   128      // chunks per batch
#define CHK   16       // steps per chunk
#define NSEG  8        // segments per batch (NCH / CHK)
#define SIZE  4680     // 8 + 64 + 512 + 4096
#define STRIDE 4736    // padded row stride (floats)
#define O2    8
#define O3    72
#define O4    584
#define HDIM  256
#define NSL   16       // gemv slices

// Scratch (device globals -- no runtime allocation)
__device__ float g_bufA[(size_t)BB * NCH * STRIDE];   // chunk sigs, later logs
__device__ float g_bufB[(size_t)BB * NCH * STRIDE];   // local prefixes
__device__ float g_T[(size_t)BB * NSEG * STRIDE];     // scanned totals P[1..7]
__device__ float g_pool[BB * SIZE];
__device__ float g_hp[NSL * BB * HDIM];

// ---------------------------------------------------------------------------
// Kernel 1: per-chunk signature via Chen iteration of exp(d_s) factors.
// (unchanged from round 3 — passing & fast enough for now)
// ---------------------------------------------------------------------------
__global__ void __launch_bounds__(256) k_chunksig(const float* __restrict__ x)
{
    int blk = blockIdx.x;          // b*NCH + n
    int b = blk >> 7, n = blk & 127;
    int tid = threadIdx.x;

    __shared__ float d[CHK][CC];
    __shared__ __align__(16) float c[O4];

    if (tid < CHK * CC) {
        int s = tid >> 3, ch = tid & 7;
        int t = n * CHK + s;
        float v;
        if (ch < CIN) {
            float cur  = x[(b * TT + t) * CIN + ch];
            float prev = (t > 0) ? x[(b * TT + t - 1) * CIN + ch] : 0.0f;
            v = cur - prev;
        } else {
            v = (t > 0) ? (1.0f / 2047.0f) : 0.0f;
        }
        d[s][ch] = v;
    }
    __syncthreads();

    const int l = tid & 7, k = (tid >> 3) & 7, j0 = tid >> 6;
    float r4[16];

    {
        float d8[8];
        #pragma unroll
        for (int i = 0; i < 8; i++) d8[i] = d[0][i];
        float dl = d8[l], dk = d8[k], dkl = dk * dl;
        float dje = d8[j0], djo = d8[j0 + 4];
        #pragma unroll
        for (int m = 0; m < 16; m++) {
            float dj = (m & 1) ? djo : dje;
            r4[m] = d8[m >> 1] * dj * dkl * (1.0f / 24.0f);
        }
        c[O3 + tid]       = dje * dkl * (1.0f / 6.0f);
        c[O3 + tid + 256] = djo * dkl * (1.0f / 6.0f);
        if (tid < 64) c[O2 + tid] = d8[tid >> 3] * d8[tid & 7] * 0.5f;
        if (tid < 8)  c[tid] = d8[tid];
    }

    for (int s = 1; s < CHK; s++) {
        __syncthreads();
        float d8[8], c1r[8];
        #pragma unroll
        for (int i = 0; i < 8; i++) d8[i] = d[s][i];
        #pragma unroll
        for (int i = 0; i < 8; i++) c1r[i] = c[i];
        float dl = d8[l], dk = d8[k], dkl = dk * dl;
        float dje = d8[j0], djo = d8[j0 + 4];
        float djkle = dje * dkl, djklo = djo * dkl;
        float hdkl = 0.5f * dkl;
        #pragma unroll
        for (int m = 0; m < 16; m++) {
            float c3 = c[O3 + (tid >> 3) + 32 * m];
            float c2 = c[O2 + (tid >> 6) + 4 * m];
            float djkl = (m & 1) ? djklo : djkle;
            r4[m] += c3 * dl + c2 * hdkl
                   + c1r[m >> 1] * ((1.0f / 6.0f) * djkl)
                   + d8[m >> 1] * djkl * (1.0f / 24.0f);
        }
        float cO3a = c[O3 + tid], cO3b = c[O3 + tid + 256];
        float c2qa = c[O2 + (tid >> 3)], c2qb = c[O2 + (tid >> 3) + 32];
        float t3a = cO3a + c2qa * dl + c1r[j0]     * hdkl + djkle * (1.0f / 6.0f);
        float t3b = cO3b + c2qb * dl + c1r[j0 + 4] * hdkl + djklo * (1.0f / 6.0f);
        float t2 = 0.0f, t1 = 0.0f;
        if (tid < 64) t2 = c[O2 + tid] + c1r[tid >> 3] * d8[tid & 7]
                         + d8[tid >> 3] * d8[tid & 7] * 0.5f;
        if (tid < 8)  t1 = c1r[tid] + d8[tid];
        __syncthreads();
        c[O3 + tid] = t3a; c[O3 + tid + 256] = t3b;
        if (tid < 64) c[O2 + tid] = t2;
        if (tid < 8)  c[tid] = t1;
    }
    __syncthreads();

    float* o = g_bufA + (size_t)blk * STRIDE;
    for (int t = tid; t < O4; t += 256) o[t] = c[t];
    #pragma unroll
    for (int m = 0; m < 16; m++) o[O4 + tid + 256 * m] = r4[m];
}

// ---------------------------------------------------------------------------
// Kernel 2: serial local prefix product within each 16-chunk segment.
// 64 blocks x 512 threads. L4 carry in float4 regs (2/thread); lows
// double-buffered; L4 global traffic vectorized (float4).
// Thread owns p = 4*tid + 2048*m2 + e, m2 in {0,1}, e in 0..3.
// ---------------------------------------------------------------------------
__global__ void __launch_bounds__(512) k_segscan()
{
    int blk = blockIdx.x;
    int tid = threadIdx.x;
    __shared__ __align__(16) float c[O4];
    __shared__ __align__(16) float bl[2][O4];

    size_t base = (size_t)blk * CHK * STRIDE;
    const float* A0 = g_bufA + base;
    float* Out = g_bufB + base;

    float4 r4v[2];
    for (int t = tid; t < O4; t += 512) { float v = A0[t]; c[t] = v; Out[t] = v; }
    #pragma unroll
    for (int m2 = 0; m2 < 2; m2++) {
        int p = 4 * tid + 2048 * m2;
        float4 v = *(const float4*)&A0[O4 + p];
        r4v[m2] = v;
        *(float4*)&Out[O4 + p] = v;
    }
    {
        const float* A1 = A0 + STRIDE;
        for (int t = tid; t < O4; t += 512) bl[0][t] = A1[t];
    }

    for (int ci = 1; ci < CHK; ci++) {
        int cur = (ci - 1) & 1, nxt = ci & 1;
        __syncthreads();
        if (ci + 1 < CHK) {
            const float* An = A0 + (size_t)(ci + 1) * STRIDE;
            for (int t = tid; t < O4; t += 512) bl[nxt][t] = An[t];
        }
        const float* Bg = A0 + (size_t)ci * STRIDE;
        const float* bb = bl[cur];

        float4 b1v = *(const float4*)&bb[(4 * tid) & 7];
        float4 b2v = *(const float4*)&bb[O2 + ((4 * tid) & 63)];
        float4 b3v = *(const float4*)&bb[O3 + 4 * (tid & 127)];
        float c1r[8];
        #pragma unroll
        for (int i = 0; i < 8; i++) c1r[i] = c[i];

        #pragma unroll
        for (int m2 = 0; m2 < 2; m2++) {
            int p = 4 * tid + 2048 * m2;
            float a1 = c1r[(tid >> 7) + 4 * m2];
            float a2 = c[O2 + (tid >> 4) + 32 * m2];
            float a3 = c[O3 + (tid >> 1) + 256 * m2];
            float4 Bv = *(const float4*)&Bg[O4 + p];
            r4v[m2].x += Bv.x + a1 * b3v.x + a2 * b2v.x + a3 * b1v.x;
            r4v[m2].y += Bv.y + a1 * b3v.y + a2 * b2v.y + a3 * b1v.y;
            r4v[m2].z += Bv.z + a1 * b3v.z + a2 * b2v.z + a3 * b1v.z;
            r4v[m2].w += Bv.w + a1 * b3v.w + a2 * b2v.w + a3 * b1v.w;
        }
        float b3s = bb[O3 + tid], b2s = bb[O2 + (tid & 63)], b1s = bb[tid & 7];
        float t3 = c[O3 + tid] + b3s + c1r[tid >> 6] * b2s + c[O2 + (tid >> 3)] * b1s;
        float t2 = 0.0f, t1 = 0.0f;
        if (tid < 64) t2 = c[O2 + tid] + bb[O2 + tid] + c1r[tid >> 3] * bb[tid & 7];
        if (tid < 8)  t1 = c1r[tid] + bb[tid];
        __syncthreads();
        c[O3 + tid] = t3;
        if (tid < 64) c[O2 + tid] = t2;
        if (tid < 8)  c[tid] = t1;
        float* Op = Out + (size_t)ci * STRIDE;
        Op[O3 + tid] = t3;
        if (tid < 64) Op[O2 + tid] = t2;
        if (tid < 8)  Op[tid] = t1;
        #pragma unroll
        for (int m2 = 0; m2 < 2; m2++)
            *(float4*)&Op[O4 + 4 * tid + 2048 * m2] = r4v[m2];
    }
}

// ---------------------------------------------------------------------------
// Kernel 3: Sklansky inclusive scan of the 8 segment totals. 8 blocks x 512
// threads (4 groups of 128, one mul per group per round, depth 3).
// Lows of all 8 totals live in smem; L4 intermediates in g_T (L2-hot).
// P[s] for s=1..7 ends in g_T row s; P[0] stays = bufB total row 0.
// ---------------------------------------------------------------------------
__global__ void __launch_bounds__(512) k_offsets_sk()
{
    int b = blockIdx.x;
    int tid = threadIdx.x;
    int g = tid >> 7, gt = tid & 127;

    __shared__ __align__(16) float low[8][O4];

    for (int s = 0; s < 8; s++) {
        const float* T = g_bufB + (size_t)(b * NCH + s * CHK + CHK - 1) * STRIDE;
        for (int t = tid; t < O4; t += 512) low[s][t] = T[t];
    }
    __syncthreads();

    const int srcT[3][4] = {{0,2,4,6},{1,1,5,5},{3,3,3,3}};
    const int dstT[3][4] = {{1,3,5,7},{2,3,6,7},{4,5,6,7}};
    const int bGT [3][4] = {{0,0,0,0},{0,1,0,1},{0,1,1,1}};

    for (int r = 0; r < 3; r++) {
        int src = srcT[r][g], dst = dstT[r][g];
        const float* A4 = (r == 0)
            ? g_bufB + (size_t)(b * NCH + src * CHK + CHK - 1) * STRIDE
            : g_T + (size_t)(b * NSEG + src) * STRIDE;
        const float* B4 = bGT[r][g]
            ? g_T + (size_t)(b * NSEG + dst) * STRIDE
            : g_bufB + (size_t)(b * NCH + dst * CHK + CHK - 1) * STRIDE;
        float* Od = g_T + (size_t)(b * NSEG + dst) * STRIDE;

        const float* as = low[src];
        float* bs = low[dst];

        float4 b1v = *(const float4*)&bs[(4 * gt) & 7];
        float4 b2v = *(const float4*)&bs[O2 + ((4 * gt) & 63)];
        float4 b3v = *(const float4*)&bs[O3 + 4 * gt];

        float4 r4o[8];
        #pragma unroll
        for (int m = 0; m < 8; m++) {
            int p = 4 * gt + 512 * m;
            float a1 = as[m];
            float a2 = as[O2 + (gt >> 4) + 8 * m];
            float a3 = as[O3 + (gt >> 1) + 64 * m];
            float4 Av = *(const float4*)&A4[O4 + p];
            float4 Bv = *(const float4*)&B4[O4 + p];
            float4 o;
            o.x = Av.x + Bv.x + a1 * b3v.x + a2 * b2v.x + a3 * b1v.x;
            o.y = Av.y + Bv.y + a1 * b3v.y + a2 * b2v.y + a3 * b1v.y;
            o.z = Av.z + Bv.z + a1 * b3v.z + a2 * b2v.z + a3 * b1v.z;
            o.w = Av.w + Bv.w + a1 * b3v.w + a2 * b2v.w + a3 * b1v.w;
            r4o[m] = o;
        }
        // new lows (computed into regs; written after block-wide sync)
        float4 a3v = *(const float4*)&as[O3 + 4 * gt];
        float a1q = as[gt >> 4];
        float a2q = as[O2 + (gt >> 1)];
        float4 t3;
        t3.x = a3v.x + b3v.x + a1q * b2v.x + a2q * b1v.x;
        t3.y = a3v.y + b3v.y + a1q * b2v.y + a2q * b1v.y;
        t3.z = a3v.z + b3v.z + a1q * b2v.z + a2q * b1v.z;
        t3.w = a3v.w + b3v.w + a1q * b2v.w + a2q * b1v.w;
        float t2 = 0.0f, t1 = 0.0f;
        if (gt < 64) t2 = as[O2 + gt] + bs[O2 + gt] + as[gt >> 3] * bs[gt & 7];
        if (gt < 8)  t1 = as[gt] + bs[gt];
        __syncthreads();   // all reads done
        #pragma unroll
        for (int m = 0; m < 8; m++)
            *(float4*)&Od[O4 + 4 * gt + 512 * m] = r4o[m];
        *(float4*)&bs[O3 + 4 * gt] = t3;
        if (gt < 64) bs[O2 + gt] = t2;
        if (gt < 8)  bs[gt] = t1;
        __syncthreads();   // writes visible for next round
    }

    // write lows of P[1..7] to g_T (L4 already there)
    for (int s = 1; s < 8; s++) {
        float* Od = g_T + (size_t)(b * NSEG + s) * STRIDE;
        for (int t = tid; t < O4; t += 512) Od[t] = low[s][t];
    }
}

// ---------------------------------------------------------------------------
// Kernel 4: fused apply (offset (x) local) + truncated log -> g_bufA.
// L4 accumulator in float4 regs; all L4 global traffic vectorized.
// Thread owns p = 4*tid + 1024*m4 + e, m4 in 0..3.
// ---------------------------------------------------------------------------
__global__ void __launch_bounds__(256) k_apply_log()
{
    int blk = blockIdx.x;                 // b*NCH + n
    int b = blk >> 7, n = blk & 127;
    int seg = n >> 4;
    int tid = threadIdx.x;

    __shared__ __align__(16) float s[O4];
    __shared__ __align__(16) float al[O4];
    __shared__ __align__(16) float blw[O4];
    __shared__ __align__(16) float P2_2[64];
    __shared__ __align__(16) float P2_3[512];
    __shared__ __align__(16) float P3_3[512];

    const float* L = g_bufB + (size_t)blk * STRIDE;
    float4 r4v[4];

    if (seg == 0) {
        for (int t = tid; t < O4; t += 256) s[t] = L[t];
        #pragma unroll
        for (int m4 = 0; m4 < 4; m4++)
            r4v[m4] = *(const float4*)&L[O4 + 4 * tid + 1024 * m4];
    } else {
        const float* A = (seg == 1)
            ? g_bufB + (size_t)(b * NCH + CHK - 1) * STRIDE
            : g_T + (size_t)(b * NSEG + seg - 1) * STRIDE;
        for (int t = tid; t < O4; t += 256) { al[t] = A[t]; blw[t] = L[t]; }
        __syncthreads();
        for (int t = tid; t < O4; t += 256) {
            float r;
            if (t >= O3) {
                int q = t - O3;
                r = al[t] + blw[t]
                  + al[q >> 6]        * blw[O2 + (q & 63)]
                  + al[O2 + (q >> 3)] * blw[q & 7];
            } else if (t >= O2) {
                int u = t - O2;
                r = al[t] + blw[t] + al[u >> 3] * blw[u & 7];
            } else {
                r = al[t] + blw[t];
            }
            s[t] = r;
        }
        float a1r[8];
        #pragma unroll
        for (int i = 0; i < 8; i++) a1r[i] = al[i];
        float4 b1v = *(const float4*)&blw[(4 * tid) & 7];
        float4 b2v = *(const float4*)&blw[O2 + ((4 * tid) & 63)];
        float4 b3v = *(const float4*)&blw[O3 + 4 * (tid & 127)];
        #pragma unroll
        for (int m4 = 0; m4 < 4; m4++) {
            int p = 4 * tid + 1024 * m4;
            float a1 = a1r[(tid >> 7) + 2 * m4];
            float a2 = al[O2 + (tid >> 4) + 16 * m4];
            float a3 = al[O3 + (tid >> 1) + 128 * m4];
            float4 Av = *(const float4*)&A[O4 + p];
            float4 Lv = *(const float4*)&L[O4 + p];
            float4 o;
            o.x = Av.x + Lv.x + a1 * b3v.x + a2 * b2v.x + a3 * b1v.x;
            o.y = Av.y + Lv.y + a1 * b3v.y + a2 * b2v.y + a3 * b1v.y;
            o.z = Av.z + Lv.z + a1 * b3v.z + a2 * b2v.z + a3 * b1v.z;
            o.w = Av.w + Lv.w + a1 * b3v.w + a2 * b2v.w + a3 * b1v.w;
            r4v[m4] = o;
        }
    }
    __syncthreads();

    // ---- truncated log, folded into r4v ----
    float s1r[8];
    #pragma unroll
    for (int i = 0; i < 8; i++) s1r[i] = s[i];
    float4 s1v = *(const float4*)&s[(4 * tid) & 7];
    float4 s2v = *(const float4*)&s[O2 + ((4 * tid) & 63)];
    float4 s3v = *(const float4*)&s[O3 + 4 * (tid & 127)];
    float s2f = s[O2 + (tid & 63)], s1f = s[tid & 7];
    float s3a = s[O3 + tid], s3b = s[O3 + tid + 256];

    // p2: fold -1/2 p2_L4; store p2 lows
    #pragma unroll
    for (int m4 = 0; m4 < 4; m4++) {
        float a1 = s1r[(tid >> 7) + 2 * m4];
        float a2 = s[O2 + (tid >> 4) + 16 * m4];
        float a3 = s[O3 + (tid >> 1) + 128 * m4];
        r4v[m4].x -= 0.5f * (a1 * s3v.x + a2 * s2v.x + a3 * s1v.x);
        r4v[m4].y -= 0.5f * (a1 * s3v.y + a2 * s2v.y + a3 * s1v.y);
        r4v[m4].z -= 0.5f * (a1 * s3v.z + a2 * s2v.z + a3 * s1v.z);
        r4v[m4].w -= 0.5f * (a1 * s3v.w + a2 * s2v.w + a3 * s1v.w);
    }
    {
        float pa = s1r[tid >> 6] * s2f + s[O2 + (tid >> 3)] * s1f;
        float pb = s1r[(tid >> 6) + 4] * s2f + s[O2 + (tid >> 3) + 32] * s1f;
        P2_3[tid] = pa; P2_3[tid + 256] = pb;
    }
    if (tid < 64) P2_2[tid] = s1r[tid >> 3] * s[tid & 7];
    __syncthreads();

    // p3: fold +1/3 p3_L4; store p3 level 3
    {
        float4 P23v = *(const float4*)&P2_3[4 * (tid & 127)];
        float4 P22v = *(const float4*)&P2_2[(4 * tid) & 63];
        #pragma unroll
        for (int m4 = 0; m4 < 4; m4++) {
            float a1 = s1r[(tid >> 7) + 2 * m4];
            float a2 = s[O2 + (tid >> 4) + 16 * m4];
            r4v[m4].x += (1.0f / 3.0f) * (a1 * P23v.x + a2 * P22v.x);
            r4v[m4].y += (1.0f / 3.0f) * (a1 * P23v.y + a2 * P22v.y);
            r4v[m4].z += (1.0f / 3.0f) * (a1 * P23v.z + a2 * P22v.z);
            r4v[m4].w += (1.0f / 3.0f) * (a1 * P23v.w + a2 * P22v.w);
        }
        float P22a = P2_2[tid & 63];
        P3_3[tid]       = s1r[tid >> 6] * P22a;
        P3_3[tid + 256] = s1r[(tid >> 6) + 4] * P22a;
    }
    __syncthreads();

    // p4: fold -1/4 p4_L4; write out
    float* S = g_bufA + (size_t)blk * STRIDE;
    {
        float4 P33v = *(const float4*)&P3_3[4 * (tid & 127)];
        #pragma unroll
        for (int m4 = 0; m4 < 4; m4++) {
            float a1 = s1r[(tid >> 7) + 2 * m4];
            r4v[m4].x -= 0.25f * a1 * P33v.x;
            r4v[m4].y -= 0.25f * a1 * P33v.y;
            r4v[m4].z -= 0.25f * a1 * P33v.z;
            r4v[m4].w -= 0.25f * a1 * P33v.w;
            *(float4*)&S[O4 + 4 * tid + 1024 * m4] = r4v[m4];
        }
        S[O3 + tid]       = s3a - 0.5f * P2_3[tid]       + (1.0f / 3.0f) * P3_3[tid];
        S[O3 + tid + 256] = s3b - 0.5f * P2_3[tid + 256] + (1.0f / 3.0f) * P3_3[tid + 256];
    }
    if (tid < 64) S[O2 + tid] = s[O2 + tid] - 0.5f * P2_2[tid];
    if (tid < 8)  S[tid] = s1r[tid];
}

// ---------------------------------------------------------------------------
// Kernel 5: mean over chunk dim -> pooled (B, SIZE)
// ---------------------------------------------------------------------------
__global__ void __launch_bounds__(256) k_pool()
{
    int g = blockIdx.x * 256 + threadIdx.x;
    if (g >= BB * SIZE) return;
    int b = g / SIZE, i = g - b * SIZE;
    const float* p = g_bufA + (size_t)b * NCH * STRIDE + i;
    float acc = 0.0f;
    #pragma unroll 8
    for (int n = 0; n < NCH; n++) acc += p[(size_t)n * STRIDE];
    g_pool[g] = acc * (1.0f / NCH);
}

// ---------------------------------------------------------------------------
// MLP: gemv partials (no atomics), then reduce + relu + out
// ---------------------------------------------------------------------------
__global__ void __launch_bounds__(256) k_gemv1(const float* __restrict__ W1)
{
    int b = blockIdx.x, sl = blockIdx.y;
    int j = threadIdx.x;
    int i0 = sl * 293;
    int i1 = i0 + 293; if (i1 > SIZE) i1 = SIZE;
    const float* pv = g_pool + b * SIZE;
    float acc = 0.0f;
    #pragma unroll 4
    for (int i = i0; i < i1; i++)
        acc = fmaf(__ldg(&pv[i]), __ldg(&W1[(size_t)i * HDIM + j]), acc);
    g_hp[(sl * BB + b) * HDIM + j] = acc;
}

__global__ void __launch_bounds__(256) k_out(const float* __restrict__ b1,
                                             const float* __restrict__ W2,
                                             const float* __restrict__ b2,
                                             float* __restrict__ out)
{
    int b = blockIdx.x, j = threadIdx.x;
    float h = 0.0f;
    #pragma unroll
    for (int sl = 0; sl < NSL; sl++) h += g_hp[(sl * BB + b) * HDIM + j];
    float v = fmaxf(h + b1[j], 0.0f) * W2[j];
    __shared__ float red[256];
    red[j] = v; __syncthreads();
    for (int s2 = 128; s2 > 0; s2 >>= 1) {
        if (j < s2) red[j] += red[j + s2];
        __syncthreads();
    }
    if (j == 0) out[b] = red[0] + b2[0];
}

// ---------------------------------------------------------------------------
extern "C" void kernel_launch(void* const* d_in, const int* in_sizes, int n_in,
                              void* d_out, int out_size)
{
    const float* x  = (const float*)d_in[0];
    const float* W1 = (const float*)d_in[1];
    const float* b1 = (const float*)d_in[2];
    const float* W2 = (const float*)d_in[3];
    const float* b2 = (const float*)d_in[4];
    float* out = (float*)d_out;

    (void)in_sizes; (void)n_in; (void)out_size;

    k_chunksig<<<BB * NCH, 256>>>(x);
    k_segscan<<<BB * NSEG, 512>>>();
    k_offsets_sk<<<BB, 512>>>();
    k_apply_log<<<BB * NCH, 256>>>();
    k_pool<<<(BB * SIZE + 255) / 256, 256>>>();
    dim3 g1(BB, NSL);
    k_gemv1<<<g1, 256>>>(W1);
    k_out<<<BB, 256>>>(b1, W2, b2, out);
}